// round 11
// baseline (speedup 1.0000x reference)
#include <cuda_runtime.h>

typedef unsigned long long u64;

#define NSTEP 256   // C2
#define NTH   128   // threads per block; thread t owns complex elements 8t..8t+7
#define SGN   0x8000000080000000ULL

// Compact coefficient streams: [step][chunk 0..11][thread], 256*12*128*16B = 6.29 MB.
__device__ float4 gC[NSTEP * 12 * NTH];

__device__ __forceinline__ u64 pk2(float x) {
    u64 r; asm("mov.b64 %0, {%1, %1};" : "=l"(r) : "f"(x)); return r;
}
__device__ __forceinline__ u64 pk(float lo, float hi) {
    u64 r; asm("mov.b64 %0, {%1, %2};" : "=l"(r) : "f"(lo), "f"(hi)); return r;
}
__device__ __forceinline__ void upk(u64 v, float& lo, float& hi) {
    asm("mov.b64 {%0, %1}, %2;" : "=f"(lo), "=f"(hi) : "l"(v));
}
__device__ __forceinline__ u64 mul2(u64 a, u64 b) {
    u64 r; asm("mul.rn.f32x2 %0, %1, %2;" : "=l"(r) : "l"(a), "l"(b)); return r;
}
__device__ __forceinline__ u64 fma2(u64 a, u64 b, u64 c) {
    u64 r; asm("fma.rn.f32x2 %0, %1, %2, %3;" : "=l"(r) : "l"(a), "l"(b), "l"(c)); return r;
}
__device__ __forceinline__ void barsync(int id) {
    asm volatile("bar.sync %0, 64;" :: "r"(id) : "memory");
}

// Full local pair rotation on 2 row-groups: (f,s) -> (d*f + o*s, ct*s + st*f).
__device__ __forceinline__ void rotpair(u64* fr, u64* fi, u64* sr, u64* si,
                                        float4 cc, float ctf, float stf) {
    u64 dr = pk2(cc.x), di = pk2(cc.y), orr = pk2(cc.z), oi = pk2(cc.w);
    u64 nd = di ^ SGN, no = oi ^ SGN, ct = pk2(ctf), st = pk2(stf);
#pragma unroll
    for (int g = 0; g < 2; g++) {
        u64 ar = mul2(dr, fr[g]); ar = fma2(nd, fi[g], ar);
        ar = fma2(orr, sr[g], ar); ar = fma2(no, si[g], ar);
        u64 ai = mul2(dr, fi[g]); ai = fma2(di, fr[g], ai);
        ai = fma2(orr, si[g], ai); ai = fma2(oi, sr[g], ai);
        u64 br = mul2(ct, sr[g]); br = fma2(st, fr[g], br);
        u64 bi = mul2(ct, si[g]); bi = fma2(st, fi[g], bi);
        fr[g] = ar; fi[g] = ai; sr[g] = br; si[g] = bi;
    }
}

// phi/theta arrays: (H2=512, C2=256) row-major -> [p*256 + c]
__global__ void coeff_kernel(const float* __restrict__ phi0, const float* __restrict__ th0,
                             const float* __restrict__ phi1, const float* __restrict__ th1) {
    int idx = blockIdx.x * blockDim.x + threadIdx.x;
    if (idx >= NSTEP * 512) return;
    int p = idx & 511;     // pair index
    int c = idx >> 9;      // step
    int t = p >> 2;        // owning eunn-thread (0..127)
    int k = p & 3;         // pair slot within thread
    int base = c * 12 * NTH;
    float* F = (float*)gC;

    float sp, cp, st, ct;
    sincosf(phi0[p * NSTEP + c], &sp, &cp);
    sincosf(th0[p * NSTEP + c], &st, &ct);
    gC[base + k * NTH + t] = make_float4(cp * ct, sp * ct, -cp * st, -sp * st);
    {
        int chunk = 4 + (k >> 1), off = (k & 1) * 2;
        F[(base + chunk * NTH + t) * 4 + off]     = ct;
        F[(base + chunk * NTH + t) * 4 + off + 1] = st;
    }

    sincosf(phi1[p * NSTEP + c], &sp, &cp);
    sincosf(th1[p * NSTEP + c], &st, &ct);
    gC[base + (6 + k) * NTH + t] = make_float4(cp * ct, sp * ct, -cp * st, -sp * st);
    if (k < 2) {
        F[(base + 10 * NTH + t) * 4 + k * 2]     = ct;
        F[(base + 10 * NTH + t) * 4 + k * 2 + 1] = st;
    } else if (k == 2) {
        F[(base + 11 * NTH + t) * 4 + 0] = ct;
        F[(base + 11 * NTH + t) * 4 + 1] = st;
    } else {
        // pair 4t+3's (ct,st) is consumed as "previous pair" by thread t+1 (mod 128)
        int ts = (t + 1) & (NTH - 1);
        F[(base + 11 * NTH + ts) * 4 + 2] = ct;
        F[(base + 11 * NTH + ts) * 4 + 3] = st;
    }
}

__global__ void __launch_bounds__(NTH, 4)
eunn_kernel(const float4* __restrict__ xin, float4* __restrict__ xout) {
    const int t    = threadIdx.x;
    const int lane = t & 31;
    const int w    = t >> 5;           // 4 warps in a ring
    const int row0 = blockIdx.x * 4;   // 4 batch rows per block (2 f32x2 groups)

    // Pairwise named-barrier ids (2-coloring of the 4-warp ring):
    // even edges {0:(w0,w1), 2:(w2,w3)} then odd edges {1:(w1,w2), 3:(w3,w0)}
    const int bar_even = (w & 2);                    // w0,w1 -> 0 ; w2,w3 -> 2
    const int bar_odd  = ((w + 1) & 2) ? 1 : 3;      // w1,w2 -> 1 ; w3,w0 -> 3

    u64 er[8][2], ei[8][2];
#pragma unroll
    for (int g = 0; g < 2; g++) {
        size_t r0 = (size_t)(row0 + 2 * g) * 512;
        size_t r1 = r0 + 512;
#pragma unroll
        for (int j = 0; j < 4; j++) {
            float4 a = xin[r0 + 4 * t + j];
            float4 b = xin[r1 + 4 * t + j];
            er[2 * j][g]     = pk(a.x, b.x); ei[2 * j][g]     = pk(a.y, b.y);
            er[2 * j + 1][g] = pk(a.z, b.z); ei[2 * j + 1][g] = pk(a.w, b.w);
        }
    }

    // Double-buffered warp-boundary exchange; two pairwise named barriers per
    // step (each warp couples only to its ring neighbors, no block convoy).
    __shared__ u64 sE0r[2][2][4], sE0i[2][2][4], sE7r[2][2][4], sE7i[2][2][4];

    for (int c = 0; c < NSTEP; c++) {
        const int base = c * 12 * NTH + t;
        const int buf  = c & 1;

        // A coefficients
        float4 k0 = gC[base + 0 * NTH], k1 = gC[base + 1 * NTH];
        float4 k2 = gC[base + 2 * NTH], k3 = gC[base + 3 * NTH];
        float4 k4 = gC[base + 4 * NTH], k5 = gC[base + 5 * NTH];

        // ---- Rotation A, edge pairs first; publish immediately ----
        rotpair(er[0], ei[0], er[1], ei[1], k0, k4.x, k4.y);
        rotpair(er[6], ei[6], er[7], ei[7], k3, k5.z, k5.w);
        if (lane == 0) {
#pragma unroll
            for (int g = 0; g < 2; g++) { sE0r[buf][g][w] = er[0][g]; sE0i[buf][g][w] = ei[0][g]; }
        }
        if (lane == 31) {
#pragma unroll
            for (int g = 0; g < 2; g++) { sE7r[buf][g][w] = er[7][g]; sE7i[buf][g][w] = ei[7][g]; }
        }

        // Pairwise neighbor sync (parity-ordered; deadlock-free 2-coloring).
        barsync(bar_even);
        barsync(bar_odd);

        // ---- Rotation A, middle pairs (independent runway) ----
        rotpair(er[2], ei[2], er[3], ei[3], k1, k4.z, k4.w);
        rotpair(er[4], ei[4], er[5], ei[5], k2, k5.x, k5.y);

        // Boundary SHFLs (sources e0/e7 are final post-A); latency hidden below
        u64 nbr[2], nbi[2], pvr[2], pvi[2];
#pragma unroll
        for (int g = 0; g < 2; g++) {
            nbr[g] = __shfl_down_sync(0xffffffffu, er[0][g], 1);
            nbi[g] = __shfl_down_sync(0xffffffffu, ei[0][g], 1);
            pvr[g] = __shfl_up_sync(0xffffffffu, er[7][g], 1);
            pvi[g] = __shfl_up_sync(0xffffffffu, ei[7][g], 1);
        }

        // B coefficients (A coeffs are dead; slots reused)
        float4 k6 = gC[base + 6 * NTH], k7 = gC[base + 7 * NTH];
        float4 k8 = gC[base + 8 * NTH], k9 = gC[base + 9 * NTH];
        float4 kA = gC[base + 10 * NTH], kB = gC[base + 11 * NTH];

        // ---- Rotation B, local pairs (e1,e2), (e3,e4), (e5,e6) ----
        rotpair(er[1], ei[1], er[2], ei[2], k6, kA.x, kA.y);
        rotpair(er[3], ei[3], er[4], ei[4], k7, kA.z, kA.w);
        rotpair(er[5], ei[5], er[6], ei[6], k8, kB.x, kB.y);

        // ---- Rotation B, boundary pair: (e7, next-thread e0) ----
        {
            const int wn = (w + 1) & 3, wp = (w + 3) & 3;
#pragma unroll
            for (int g = 0; g < 2; g++) {
                if (lane == 31) { nbr[g] = sE0r[buf][g][wn]; nbi[g] = sE0i[buf][g][wn]; }
                if (lane == 0)  { pvr[g] = sE7r[buf][g][wp]; pvi[g] = sE7i[buf][g][wp]; }
            }

            u64 dr = pk2(k9.x), di = pk2(k9.y), orr = pk2(k9.z), oi = pk2(k9.w);
            u64 nd = di ^ SGN, no = oi ^ SGN, ctm = pk2(kB.z), stm = pk2(kB.w);
#pragma unroll
            for (int g = 0; g < 2; g++) {
                u64 cr = mul2(dr, er[7][g]); cr = fma2(nd, ei[7][g], cr);
                cr = fma2(orr, nbr[g], cr);  cr = fma2(no, nbi[g], cr);
                u64 ci = mul2(dr, ei[7][g]); ci = fma2(di, er[7][g], ci);
                ci = fma2(orr, nbi[g], ci);  ci = fma2(oi, nbr[g], ci);
                u64 zr = mul2(ctm, er[0][g]); zr = fma2(stm, pvr[g], zr);
                u64 zi = mul2(ctm, ei[0][g]); zi = fma2(stm, pvi[g], zi);
                er[7][g] = cr; ei[7][g] = ci; er[0][g] = zr; ei[0][g] = zi;
            }
        }
    }

#pragma unroll
    for (int g = 0; g < 2; g++) {
        size_t r0 = (size_t)(row0 + 2 * g) * 512;
        size_t r1 = r0 + 512;
#pragma unroll
        for (int j = 0; j < 4; j++) {
            float4 a, b;
            upk(er[2 * j][g], a.x, b.x);     upk(ei[2 * j][g], a.y, b.y);
            upk(er[2 * j + 1][g], a.z, b.z); upk(ei[2 * j + 1][g], a.w, b.w);
            xout[r0 + 4 * t + j] = a;
            xout[r1 + 4 * t + j] = b;
        }
    }
}

extern "C" void kernel_launch(void* const* d_in, const int* in_sizes, int n_in,
                              void* d_out, int out_size) {
    const float* x    = (const float*)d_in[0];
    const float* phi0 = (const float*)d_in[1];
    const float* th0  = (const float*)d_in[2];
    const float* phi1 = (const float*)d_in[3];
    const float* th1  = (const float*)d_in[4];

    coeff_kernel<<<(NSTEP * 512 + 255) / 256, 256>>>(phi0, th0, phi1, th1);
    eunn_kernel<<<4096 / 4, NTH>>>((const float4*)x, (float4*)d_out);
}

// round 12
// speedup vs baseline: 1.1229x; 1.1229x over previous
#include <cuda_runtime.h>

typedef unsigned long long u64;

#define NSTEP 256   // C2
#define NTH   128   // threads per block; thread t owns complex elements 8t..8t+7
#define SGN   0x8000000080000000ULL

// Compact coefficient streams: [step][chunk 0..11][thread], 256*12*128*16B = 6.29 MB.
// chunks 0..3:  rotA pairs 4t+0..3 (dr,di,or,oi)
// chunk  4:     (ctA[4t],stA[4t],ctA[4t+1],stA[4t+1])
// chunk  5:     (ctA[4t+2],stA[4t+2],ctA[4t+3],stA[4t+3])
// chunks 6..9:  rotB pairs 4t+0..3 (dr,di,or,oi)   (pair 4t+3 = boundary)
// chunk  10:    (ctB[4t],stB[4t],ctB[4t+1],stB[4t+1])
// chunk  11:    (ctB[4t+2],stB[4t+2],ctB[4t-1],stB[4t-1])  [zw pre-shifted]
__device__ float4 gC[NSTEP * 12 * NTH];

__device__ __forceinline__ u64 pk2(float x) {
    u64 r; asm("mov.b64 %0, {%1, %1};" : "=l"(r) : "f"(x)); return r;
}
__device__ __forceinline__ u64 pk(float lo, float hi) {
    u64 r; asm("mov.b64 %0, {%1, %2};" : "=l"(r) : "f"(lo), "f"(hi)); return r;
}
__device__ __forceinline__ void upk(u64 v, float& lo, float& hi) {
    asm("mov.b64 {%0, %1}, %2;" : "=f"(lo), "=f"(hi) : "l"(v));
}
__device__ __forceinline__ u64 mul2(u64 a, u64 b) {
    u64 r; asm("mul.rn.f32x2 %0, %1, %2;" : "=l"(r) : "l"(a), "l"(b)); return r;
}
__device__ __forceinline__ u64 fma2(u64 a, u64 b, u64 c) {
    u64 r; asm("fma.rn.f32x2 %0, %1, %2, %3;" : "=l"(r) : "l"(a), "l"(b), "l"(c)); return r;
}

// Full local pair rotation on 2 row-groups: (f,s) -> (d*f + o*s, ct*s + st*f).
__device__ __forceinline__ void rotpair(u64* fr, u64* fi, u64* sr, u64* si,
                                        float4 cc, float ctf, float stf) {
    u64 dr = pk2(cc.x), di = pk2(cc.y), orr = pk2(cc.z), oi = pk2(cc.w);
    u64 nd = di ^ SGN, no = oi ^ SGN, ct = pk2(ctf), st = pk2(stf);
#pragma unroll
    for (int g = 0; g < 2; g++) {
        u64 ar = mul2(dr, fr[g]); ar = fma2(nd, fi[g], ar);
        ar = fma2(orr, sr[g], ar); ar = fma2(no, si[g], ar);
        u64 ai = mul2(dr, fi[g]); ai = fma2(di, fr[g], ai);
        ai = fma2(orr, si[g], ai); ai = fma2(oi, sr[g], ai);
        u64 br = mul2(ct, sr[g]); br = fma2(st, fr[g], br);
        u64 bi = mul2(ct, si[g]); bi = fma2(st, fi[g], bi);
        fr[g] = ar; fi[g] = ai; sr[g] = br; si[g] = bi;
    }
}

// phi/theta arrays: (H2=512, C2=256) row-major -> [p*256 + c]
__global__ void coeff_kernel(const float* __restrict__ phi0, const float* __restrict__ th0,
                             const float* __restrict__ phi1, const float* __restrict__ th1) {
    int idx = blockIdx.x * blockDim.x + threadIdx.x;
    if (idx >= NSTEP * 512) return;
    int p = idx & 511;     // pair index
    int c = idx >> 9;      // step
    int t = p >> 2;        // owning eunn-thread (0..127)
    int k = p & 3;         // pair slot within thread
    int base = c * 12 * NTH;
    float* F = (float*)gC;

    float sp, cp, st, ct;
    sincosf(phi0[p * NSTEP + c], &sp, &cp);
    sincosf(th0[p * NSTEP + c], &st, &ct);
    gC[base + k * NTH + t] = make_float4(cp * ct, sp * ct, -cp * st, -sp * st);
    {
        int chunk = 4 + (k >> 1), off = (k & 1) * 2;
        F[(base + chunk * NTH + t) * 4 + off]     = ct;
        F[(base + chunk * NTH + t) * 4 + off + 1] = st;
    }

    sincosf(phi1[p * NSTEP + c], &sp, &cp);
    sincosf(th1[p * NSTEP + c], &st, &ct);
    gC[base + (6 + k) * NTH + t] = make_float4(cp * ct, sp * ct, -cp * st, -sp * st);
    if (k < 2) {
        F[(base + 10 * NTH + t) * 4 + k * 2]     = ct;
        F[(base + 10 * NTH + t) * 4 + k * 2 + 1] = st;
    } else if (k == 2) {
        F[(base + 11 * NTH + t) * 4 + 0] = ct;
        F[(base + 11 * NTH + t) * 4 + 1] = st;
    } else {
        // pair 4t+3's (ct,st) is consumed as "previous pair" by thread t+1 (mod 128)
        int ts = (t + 1) & (NTH - 1);
        F[(base + 11 * NTH + ts) * 4 + 2] = ct;
        F[(base + 11 * NTH + ts) * 4 + 3] = st;
    }
}

__global__ void __launch_bounds__(NTH, 5)
eunn_kernel(const float4* __restrict__ xin, float4* __restrict__ xout) {
    const int t    = threadIdx.x;
    const int lane = t & 31;
    const int w    = t >> 5;           // 4 warps
    const int row0 = blockIdx.x * 4;   // 4 batch rows per block (2 f32x2 groups)

    u64 er[8][2], ei[8][2];
#pragma unroll
    for (int g = 0; g < 2; g++) {
        size_t r0 = (size_t)(row0 + 2 * g) * 512;
        size_t r1 = r0 + 512;
#pragma unroll
        for (int j = 0; j < 4; j++) {
            float4 a = xin[r0 + 4 * t + j];
            float4 b = xin[r1 + 4 * t + j];
            er[2 * j][g]     = pk(a.x, b.x); ei[2 * j][g]     = pk(a.y, b.y);
            er[2 * j + 1][g] = pk(a.z, b.z); ei[2 * j + 1][g] = pk(a.w, b.w);
        }
    }

    // Double-buffered warp-boundary exchange; one __syncthreads per step.
    __shared__ u64 sE0r[2][2][4], sE0i[2][2][4], sE7r[2][2][4], sE7i[2][2][4];

    for (int c = 0; c < NSTEP; c++) {
        const int base = c * 12 * NTH + t;
        const int buf  = c & 1;

        // ---- Rotation A: coefficients staged per rotation (low reg pressure) ----
        {
            float4 k0 = gC[base + 0 * NTH];
            float4 k4 = gC[base + 4 * NTH];
            rotpair(er[0], ei[0], er[1], ei[1], k0, k4.x, k4.y);
            float4 k1 = gC[base + 1 * NTH];
            rotpair(er[2], ei[2], er[3], ei[3], k1, k4.z, k4.w);
            float4 k2 = gC[base + 2 * NTH];
            float4 k5 = gC[base + 5 * NTH];
            rotpair(er[4], ei[4], er[5], ei[5], k2, k5.x, k5.y);
            float4 k3 = gC[base + 3 * NTH];
            rotpair(er[6], ei[6], er[7], ei[7], k3, k5.z, k5.w);
        }

        // Edge publish (post-rotA e0 / e7 are final until the boundary rotation)
        if (lane == 0) {
#pragma unroll
            for (int g = 0; g < 2; g++) { sE0r[buf][g][w] = er[0][g]; sE0i[buf][g][w] = ei[0][g]; }
        }
        if (lane == 31) {
#pragma unroll
            for (int g = 0; g < 2; g++) { sE7r[buf][g][w] = er[7][g]; sE7i[buf][g][w] = ei[7][g]; }
        }

        // ---- Rotation B, local pairs: staged loads, pre-barrier ----
        {
            float4 k6 = gC[base + 6 * NTH];
            float4 kA = gC[base + 10 * NTH];
            rotpair(er[1], ei[1], er[2], ei[2], k6, kA.x, kA.y);
            float4 k7 = gC[base + 7 * NTH];
            rotpair(er[3], ei[3], er[4], ei[4], k7, kA.z, kA.w);
            float4 k8 = gC[base + 8 * NTH];
            float4 kB0 = gC[base + 11 * NTH];   // (ctB[4t+2], stB[4t+2], ct_prev, st_prev)
            rotpair(er[5], ei[5], er[6], ei[6], k8, kB0.x, kB0.y);

            __syncthreads();

            // ---- Rotation B, boundary pair: (e7, next-thread e0) ----
            float4 k9 = gC[base + 9 * NTH];
            const int wn = (w + 1) & 3, wp = (w + 3) & 3;
            u64 dr = pk2(k9.x), di = pk2(k9.y), orr = pk2(k9.z), oi = pk2(k9.w);
            u64 nd = di ^ SGN, no = oi ^ SGN, ctm = pk2(kB0.z), stm = pk2(kB0.w);
#pragma unroll
            for (int g = 0; g < 2; g++) {
                u64 nbr = __shfl_down_sync(0xffffffffu, er[0][g], 1);
                u64 nbi = __shfl_down_sync(0xffffffffu, ei[0][g], 1);
                u64 pvr = __shfl_up_sync(0xffffffffu, er[7][g], 1);
                u64 pvi = __shfl_up_sync(0xffffffffu, ei[7][g], 1);
                if (lane == 31) { nbr = sE0r[buf][g][wn]; nbi = sE0i[buf][g][wn]; }
                if (lane == 0)  { pvr = sE7r[buf][g][wp]; pvi = sE7i[buf][g][wp]; }

                u64 cr = mul2(dr, er[7][g]); cr = fma2(nd, ei[7][g], cr);
                cr = fma2(orr, nbr, cr);     cr = fma2(no, nbi, cr);
                u64 ci = mul2(dr, ei[7][g]); ci = fma2(di, er[7][g], ci);
                ci = fma2(orr, nbi, ci);     ci = fma2(oi, nbr, ci);
                u64 zr = mul2(ctm, er[0][g]); zr = fma2(stm, pvr, zr);
                u64 zi = mul2(ctm, ei[0][g]); zi = fma2(stm, pvi, zi);
                er[7][g] = cr; ei[7][g] = ci; er[0][g] = zr; ei[0][g] = zi;
            }
        }
    }

#pragma unroll
    for (int g = 0; g < 2; g++) {
        size_t r0 = (size_t)(row0 + 2 * g) * 512;
        size_t r1 = r0 + 512;
#pragma unroll
        for (int j = 0; j < 4; j++) {
            float4 a, b;
            upk(er[2 * j][g], a.x, b.x);     upk(ei[2 * j][g], a.y, b.y);
            upk(er[2 * j + 1][g], a.z, b.z); upk(ei[2 * j + 1][g], a.w, b.w);
            xout[r0 + 4 * t + j] = a;
            xout[r1 + 4 * t + j] = b;
        }
    }
}

extern "C" void kernel_launch(void* const* d_in, const int* in_sizes, int n_in,
                              void* d_out, int out_size) {
    const float* x    = (const float*)d_in[0];
    const float* phi0 = (const float*)d_in[1];
    const float* th0  = (const float*)d_in[2];
    const float* phi1 = (const float*)d_in[3];
    const float* th1  = (const float*)d_in[4];

    coeff_kernel<<<(NSTEP * 512 + 255) / 256, 256>>>(phi0, th0, phi1, th1);
    eunn_kernel<<<4096 / 4, NTH>>>((const float4*)x, (float4*)d_out);
}

// round 16
// speedup vs baseline: 1.5120x; 1.3465x over previous
#include <cuda_runtime.h>
#include <cuda_bf16.h>
#include <cstdint>

typedef unsigned long long u64;

#define NSTEP 256
#define NTH   128
#define SGN   0x8000000080000000ULL

// ===================== scalar-scan machinery (R5, proven) =====================
__device__ float4 gC[NSTEP * 12 * NTH];

__device__ __forceinline__ u64 pk2(float x) {
    u64 r; asm("mov.b64 %0, {%1, %1};" : "=l"(r) : "f"(x)); return r;
}
__device__ __forceinline__ u64 pk(float lo, float hi) {
    u64 r; asm("mov.b64 %0, {%1, %2};" : "=l"(r) : "f"(lo), "f"(hi)); return r;
}
__device__ __forceinline__ void upk(u64 v, float& lo, float& hi) {
    asm("mov.b64 {%0, %1}, %2;" : "=f"(lo), "=f"(hi) : "l"(v));
}
__device__ __forceinline__ u64 mul2(u64 a, u64 b) {
    u64 r; asm("mul.rn.f32x2 %0, %1, %2;" : "=l"(r) : "l"(a), "l"(b)); return r;
}
__device__ __forceinline__ u64 fma2(u64 a, u64 b, u64 c) {
    u64 r; asm("fma.rn.f32x2 %0, %1, %2, %3;" : "=l"(r) : "l"(a), "l"(b), "l"(c)); return r;
}
__device__ __forceinline__ void rotpair(u64* fr, u64* fi, u64* sr, u64* si,
                                        float4 cc, float ctf, float stf) {
    u64 dr = pk2(cc.x), di = pk2(cc.y), orr = pk2(cc.z), oi = pk2(cc.w);
    u64 nd = di ^ SGN, no = oi ^ SGN, ct = pk2(ctf), st = pk2(stf);
#pragma unroll
    for (int g = 0; g < 2; g++) {
        u64 ar = mul2(dr, fr[g]); ar = fma2(nd, fi[g], ar);
        ar = fma2(orr, sr[g], ar); ar = fma2(no, si[g], ar);
        u64 ai = mul2(dr, fi[g]); ai = fma2(di, fr[g], ai);
        ai = fma2(orr, si[g], ai); ai = fma2(oi, sr[g], ai);
        u64 br = mul2(ct, sr[g]); br = fma2(st, fr[g], br);
        u64 bi = mul2(ct, si[g]); bi = fma2(st, fi[g], bi);
        fr[g] = ar; fi[g] = ai; sr[g] = br; si[g] = bi;
    }
}

__global__ void coeff_kernel(const float* __restrict__ phi0, const float* __restrict__ th0,
                             const float* __restrict__ phi1, const float* __restrict__ th1) {
    int idx = blockIdx.x * blockDim.x + threadIdx.x;
    if (idx >= NSTEP * 512) return;
    int p = idx & 511;
    int c = idx >> 9;
    int t = p >> 2;
    int k = p & 3;
    int base = c * 12 * NTH;
    float* F = (float*)gC;

    float sp, cp, st, ct;
    sincosf(phi0[p * NSTEP + c], &sp, &cp);
    sincosf(th0[p * NSTEP + c], &st, &ct);
    gC[base + k * NTH + t] = make_float4(cp * ct, sp * ct, -cp * st, -sp * st);
    {
        int chunk = 4 + (k >> 1), off = (k & 1) * 2;
        F[(base + chunk * NTH + t) * 4 + off]     = ct;
        F[(base + chunk * NTH + t) * 4 + off + 1] = st;
    }
    sincosf(phi1[p * NSTEP + c], &sp, &cp);
    sincosf(th1[p * NSTEP + c], &st, &ct);
    gC[base + (6 + k) * NTH + t] = make_float4(cp * ct, sp * ct, -cp * st, -sp * st);
    if (k < 2) {
        F[(base + 10 * NTH + t) * 4 + k * 2]     = ct;
        F[(base + 10 * NTH + t) * 4 + k * 2 + 1] = st;
    } else if (k == 2) {
        F[(base + 11 * NTH + t) * 4 + 0] = ct;
        F[(base + 11 * NTH + t) * 4 + 1] = st;
    } else {
        int ts = (t + 1) & (NTH - 1);
        F[(base + 11 * NTH + ts) * 4 + 2] = ct;
        F[(base + 11 * NTH + ts) * 4 + 3] = st;
    }
}

__global__ void __launch_bounds__(NTH, 4)
eunn_kernel(const float4* __restrict__ xin, float4* __restrict__ xout) {
    const int t    = threadIdx.x;
    const int lane = t & 31;
    const int w    = t >> 5;
    const int row0 = blockIdx.x * 4;

    u64 er[8][2], ei[8][2];
#pragma unroll
    for (int g = 0; g < 2; g++) {
        size_t r0 = (size_t)(row0 + 2 * g) * 512;
        size_t r1 = r0 + 512;
#pragma unroll
        for (int j = 0; j < 4; j++) {
            float4 a = xin[r0 + 4 * t + j];
            float4 b = xin[r1 + 4 * t + j];
            er[2 * j][g]     = pk(a.x, b.x); ei[2 * j][g]     = pk(a.y, b.y);
            er[2 * j + 1][g] = pk(a.z, b.z); ei[2 * j + 1][g] = pk(a.w, b.w);
        }
    }

    __shared__ u64 sE0r[2][2][4], sE0i[2][2][4], sE7r[2][2][4], sE7i[2][2][4];

    for (int c = 0; c < NSTEP; c++) {
        const int base = c * 12 * NTH + t;
        float4 k0 = gC[base + 0 * NTH], k1 = gC[base + 1 * NTH];
        float4 k2 = gC[base + 2 * NTH], k3 = gC[base + 3 * NTH];
        float4 k4 = gC[base + 4 * NTH], k5 = gC[base + 5 * NTH];

        rotpair(er[0], ei[0], er[1], ei[1], k0, k4.x, k4.y);
        rotpair(er[2], ei[2], er[3], ei[3], k1, k4.z, k4.w);
        rotpair(er[4], ei[4], er[5], ei[5], k2, k5.x, k5.y);
        rotpair(er[6], ei[6], er[7], ei[7], k3, k5.z, k5.w);

        const int buf = c & 1;
        if (lane == 0) {
#pragma unroll
            for (int g = 0; g < 2; g++) { sE0r[buf][g][w] = er[0][g]; sE0i[buf][g][w] = ei[0][g]; }
        }
        if (lane == 31) {
#pragma unroll
            for (int g = 0; g < 2; g++) { sE7r[buf][g][w] = er[7][g]; sE7i[buf][g][w] = ei[7][g]; }
        }

        u64 nbr[2], nbi[2], pvr[2], pvi[2];
#pragma unroll
        for (int g = 0; g < 2; g++) {
            nbr[g] = __shfl_down_sync(0xffffffffu, er[0][g], 1);
            nbi[g] = __shfl_down_sync(0xffffffffu, ei[0][g], 1);
            pvr[g] = __shfl_up_sync(0xffffffffu, er[7][g], 1);
            pvi[g] = __shfl_up_sync(0xffffffffu, ei[7][g], 1);
        }

        float4 k6 = gC[base + 6 * NTH], k7 = gC[base + 7 * NTH];
        float4 k8 = gC[base + 8 * NTH], k9 = gC[base + 9 * NTH];
        float4 kA = gC[base + 10 * NTH], kB = gC[base + 11 * NTH];

        rotpair(er[1], ei[1], er[2], ei[2], k6, kA.x, kA.y);
        rotpair(er[3], ei[3], er[4], ei[4], k7, kA.z, kA.w);
        rotpair(er[5], ei[5], er[6], ei[6], k8, kB.x, kB.y);

        __syncthreads();

        {
            const int wn = (w + 1) & 3, wp = (w + 3) & 3;
            u64 dr = pk2(k9.x), di = pk2(k9.y), orr = pk2(k9.z), oi = pk2(k9.w);
            u64 nd = di ^ SGN, no = oi ^ SGN, ctm = pk2(kB.z), stm = pk2(kB.w);
#pragma unroll
            for (int g = 0; g < 2; g++) {
                u64 xr = nbr[g], xi = nbi[g], yr = pvr[g], yi = pvi[g];
                if (lane == 31) { xr = sE0r[buf][g][wn]; xi = sE0i[buf][g][wn]; }
                if (lane == 0)  { yr = sE7r[buf][g][wp]; yi = sE7i[buf][g][wp]; }

                u64 cr = mul2(dr, er[7][g]); cr = fma2(nd, ei[7][g], cr);
                cr = fma2(orr, xr, cr);      cr = fma2(no, xi, cr);
                u64 ci = mul2(dr, ei[7][g]); ci = fma2(di, er[7][g], ci);
                ci = fma2(orr, xi, ci);      ci = fma2(oi, xr, ci);
                u64 zr = mul2(ctm, er[0][g]); zr = fma2(stm, yr, zr);
                u64 zi = mul2(ctm, ei[0][g]); zi = fma2(stm, yi, zi);
                er[7][g] = cr; ei[7][g] = ci; er[0][g] = zr; ei[0][g] = zi;
            }
        }
    }

#pragma unroll
    for (int g = 0; g < 2; g++) {
        size_t r0 = (size_t)(row0 + 2 * g) * 512;
        size_t r1 = r0 + 512;
#pragma unroll
        for (int j = 0; j < 4; j++) {
            float4 a, b;
            upk(er[2 * j][g], a.x, b.x);     upk(ei[2 * j][g], a.y, b.y);
            upk(er[2 * j + 1][g], a.z, b.z); upk(ei[2 * j + 1][g], a.w, b.w);
            xout[r0 + 4 * t + j] = a;
            xout[r1 + 4 * t + j] = b;
        }
    }
}

// ===================== GEMM route: statics =====================
__device__ float gIdent[1024 * 2048];          // identity batch (1024 rows x 1024 complex)
__device__ float gBmat[1024 * 2048];           // scan(identity): row j = U e_j
__device__ __nv_bfloat16 gXh[4096u * 2048u];   // x split hi
__device__ __nv_bfloat16 gXl[4096u * 2048u];   // x split lo
__device__ __nv_bfloat16 gWtH[2048u * 2048u];  // W^T split hi (row n = output col, col k)
__device__ __nv_bfloat16 gWtL[2048u * 2048u];  // W^T split lo

__global__ void init_identity() {
    int idx = blockIdx.x * blockDim.x + threadIdx.x;
    if (idx >= 1024 * 1024) return;
    int r = idx >> 10, i = idx & 1023;
    ((float2*)gIdent)[idx] = make_float2(r == i ? 1.0f : 0.0f, 0.0f);
}

// Wt[2i][2j]=Ure  Wt[2i][2j+1]=-Uim  Wt[2i+1][2j]=Uim  Wt[2i+1][2j+1]=Ure,  U[i][j]=gBmat[j][i]
__global__ void convert_w() {
    int idx = blockIdx.x * blockDim.x + threadIdx.x;
    if (idx >= 1024 * 1024) return;
    int i = idx & 1023, j = idx >> 10;
    float2 v = ((const float2*)gBmat)[j * 1024 + i];
    float re = v.x, im = v.y;
    __nv_bfloat16 reh = __float2bfloat16(re);
    __nv_bfloat16 rel = __float2bfloat16(re - __bfloat162float(reh));
    __nv_bfloat16 imh = __float2bfloat16(im);
    __nv_bfloat16 iml = __float2bfloat16(im - __bfloat162float(imh));
    __nv_bfloat16 nimh = __float2bfloat16(-__bfloat162float(imh));
    __nv_bfloat16 niml = __float2bfloat16(-__bfloat162float(iml));
    size_t r0 = (size_t)(2 * i) * 2048, r1 = (size_t)(2 * i + 1) * 2048;
    gWtH[r0 + 2 * j] = reh;  gWtH[r0 + 2 * j + 1] = nimh;
    gWtH[r1 + 2 * j] = imh;  gWtH[r1 + 2 * j + 1] = reh;
    gWtL[r0 + 2 * j] = rel;  gWtL[r0 + 2 * j + 1] = niml;
    gWtL[r1 + 2 * j] = iml;  gWtL[r1 + 2 * j + 1] = rel;
}

__global__ void convert_x(const float* __restrict__ x) {
    int idx = blockIdx.x * blockDim.x + threadIdx.x;
    float v = x[idx];
    __nv_bfloat16 h = __float2bfloat16(v);
    gXh[idx] = h;
    gXl[idx] = __float2bfloat16(v - __bfloat162float(h));
}

// ===================== mma.sync bf16 GEMM (sm_80-class, target-legal) =====================
// D[m,n] = sum_k A[m,k]*B[n,k];  A = Xh/Xl (4096x2048), B = WtH/WtL (2048x2048).
// Split-bf16: D = AhBh + AhBl + AlBh.
// BM=128, BN=64, BK=32; 256 threads, 8 warps (4m x 2n), warp tile 32x32.
#define ROWB   80        // smem row stride bytes (32 bf16 data + 8 pad -> conflict-free ldmatrix)
#define AH_OFF 0
#define AL_OFF 10240
#define BH_OFF 20480
#define BL_OFF 25600
#define STAGE  30720

__device__ __forceinline__ uint32_t smem_to_u32(const void* p) {
    uint32_t a;
    asm("{ .reg .u64 t; cvta.to.shared.u64 t, %1; cvt.u32.u64 %0, t; }" : "=r"(a) : "l"(p));
    return a;
}
__device__ __forceinline__ void cp16(uint32_t dst, const __nv_bfloat16* src) {
    uint64_t g; asm("cvta.to.global.u64 %0, %1;" : "=l"(g) : "l"(src));
    asm volatile("cp.async.cg.shared.global [%0], [%1], 16;" :: "r"(dst), "l"(g));
}
#define CP_COMMIT() asm volatile("cp.async.commit_group;")
#define CP_WAIT(n)  asm volatile("cp.async.wait_group %0;" :: "n"(n))

__device__ __forceinline__ void ldsm_x4(uint32_t* r, uint32_t addr) {
    asm volatile("ldmatrix.sync.aligned.m8n8.x4.shared.b16 {%0,%1,%2,%3}, [%4];"
        : "=r"(r[0]), "=r"(r[1]), "=r"(r[2]), "=r"(r[3]) : "r"(addr));
}
__device__ __forceinline__ void ldsm_x2(uint32_t* r, uint32_t addr) {
    asm volatile("ldmatrix.sync.aligned.m8n8.x2.shared.b16 {%0,%1}, [%2];"
        : "=r"(r[0]), "=r"(r[1]) : "r"(addr));
}
__device__ __forceinline__ void mma_bf16(float* c, const uint32_t* a, const uint32_t* b) {
    asm volatile("mma.sync.aligned.m16n8k16.row.col.f32.bf16.bf16.f32 "
        "{%0,%1,%2,%3}, {%4,%5,%6,%7}, {%8,%9}, {%0,%1,%2,%3};"
        : "+f"(c[0]), "+f"(c[1]), "+f"(c[2]), "+f"(c[3])
        : "r"(a[0]), "r"(a[1]), "r"(a[2]), "r"(a[3]), "r"(b[0]), "r"(b[1]));
}

__global__ void __launch_bounds__(256)
gemm_kernel(float* __restrict__ out) {
    extern __shared__ unsigned char smemBuf[];
    const uint32_t sbase = smem_to_u32(smemBuf);
    const int tid  = threadIdx.x;
    const int lane = tid & 31;
    const int wid  = tid >> 5;
    const int wm   = wid & 3;    // 0..3  -> m offset wm*32
    const int wn   = wid >> 2;   // 0..1  -> n offset wn*32
    const int m0   = blockIdx.x * 128;
    const int n0   = blockIdx.y * 64;

    auto load_stage = [&](int st, int it) {
        uint32_t sb = sbase + st * STAGE;
        int k0 = it * 32;
#pragma unroll
        for (int h = 0; h < 2; h++) {
            int c = tid + h * 256;          // 512 A chunks of 16B
            int row = c >> 2, seg = c & 3;
            size_t go = (size_t)(m0 + row) * 2048 + k0 + seg * 8;
            uint32_t d = sb + row * ROWB + seg * 16;
            cp16(d + AH_OFF, gXh + go);
            cp16(d + AL_OFF, gXl + go);
        }
        {
            int row = tid >> 2, seg = tid & 3;   // 256 B chunks
            size_t go = (size_t)(n0 + row) * 2048 + k0 + seg * 8;
            uint32_t d = sb + row * ROWB + seg * 16;
            cp16(d + BH_OFF, gWtH + go);
            cp16(d + BL_OFF, gWtL + go);
        }
        CP_COMMIT();
    };

    float acc[2][4][4];
#pragma unroll
    for (int mf = 0; mf < 2; mf++)
#pragma unroll
        for (int nf = 0; nf < 4; nf++)
#pragma unroll
            for (int q = 0; q < 4; q++) acc[mf][nf][q] = 0.0f;

    load_stage(0, 0);

    for (int it = 0; it < 64; it++) {
        if (it < 63) { load_stage((it + 1) & 1, it + 1); CP_WAIT(1); }
        else         { CP_WAIT(0); }
        __syncthreads();

        uint32_t sb = sbase + (it & 1) * STAGE;
#pragma unroll
        for (int kk = 0; kk < 32; kk += 16) {
            uint32_t ah[2][4], al[2][4], bh[4][2], bl[4][2];
#pragma unroll
            for (int mf = 0; mf < 2; mf++) {
                uint32_t row = wm * 32 + mf * 16 + (lane & 15);
                uint32_t col = kk + (lane >> 4) * 8;
                uint32_t off = row * ROWB + col * 2;
                ldsm_x4(ah[mf], sb + AH_OFF + off);
                ldsm_x4(al[mf], sb + AL_OFF + off);
            }
#pragma unroll
            for (int nf = 0; nf < 4; nf++) {
                int l = lane & 15;
                uint32_t nrow = wn * 32 + nf * 8 + (l & 7);
                uint32_t col = kk + ((l >> 3) & 1) * 8;
                uint32_t off = nrow * ROWB + col * 2;
                ldsm_x2(bh[nf], sb + BH_OFF + off);
                ldsm_x2(bl[nf], sb + BL_OFF + off);
            }
#pragma unroll
            for (int mf = 0; mf < 2; mf++)
#pragma unroll
                for (int nf = 0; nf < 4; nf++) {
                    mma_bf16(acc[mf][nf], ah[mf], bh[nf]);
                    mma_bf16(acc[mf][nf], ah[mf], bl[nf]);
                    mma_bf16(acc[mf][nf], al[mf], bh[nf]);
                }
        }
        __syncthreads();
    }

#pragma unroll
    for (int mf = 0; mf < 2; mf++)
#pragma unroll
        for (int nf = 0; nf < 4; nf++) {
            int r    = m0 + wm * 32 + mf * 16 + (lane >> 2);
            int ccol = n0 + wn * 32 + nf * 8 + (lane & 3) * 2;
            *(float2*)(out + (size_t)r * 2048 + ccol) =
                make_float2(acc[mf][nf][0], acc[mf][nf][1]);
            *(float2*)(out + (size_t)(r + 8) * 2048 + ccol) =
                make_float2(acc[mf][nf][2], acc[mf][nf][3]);
        }
}

// ===================== launch =====================
extern "C" void kernel_launch(void* const* d_in, const int* in_sizes, int n_in,
                              void* d_out, int out_size) {
    const float* x    = (const float*)d_in[0];
    const float* phi0 = (const float*)d_in[1];
    const float* th0  = (const float*)d_in[2];
    const float* phi1 = (const float*)d_in[3];
    const float* th1  = (const float*)d_in[4];

    coeff_kernel<<<(NSTEP * 512 + 255) / 256, 256>>>(phi0, th0, phi1, th1);
    init_identity<<<(1024 * 1024 + 255) / 256, 256>>>();

    void *pI = nullptr, *pB = nullptr;
    cudaGetSymbolAddress(&pI, gIdent);
    cudaGetSymbolAddress(&pB, gBmat);
    // Build U by scanning the identity basis (the scan is a linear map).
    eunn_kernel<<<1024 / 4, NTH>>>((const float4*)pI, (float4*)pB);

    convert_w<<<(1024 * 1024 + 255) / 256, 256>>>();
    convert_x<<<(4096 * 2048) / 256, 256>>>(x);

    cudaFuncSetAttribute(gemm_kernel, cudaFuncAttributeMaxDynamicSharedMemorySize, 2 * STAGE);
    gemm_kernel<<<dim3(32, 32, 1), 256, 2 * STAGE>>>((float*)d_out);
}

// round 17
// speedup vs baseline: 1.7089x; 1.1303x over previous
#include <cuda_runtime.h>
#include <cuda_bf16.h>
#include <cstdint>

typedef unsigned long long u64;

#define NSTEP 256
#define NTH   128
#define SGN   0x8000000080000000ULL

// ===================== scan coefficients =====================
__device__ float4 gC[NSTEP * 12 * NTH];

__device__ __forceinline__ u64 pk2(float x) {
    u64 r; asm("mov.b64 %0, {%1, %1};" : "=l"(r) : "f"(x)); return r;
}
__device__ __forceinline__ u64 pk(float lo, float hi) {
    u64 r; asm("mov.b64 %0, {%1, %2};" : "=l"(r) : "f"(lo), "f"(hi)); return r;
}
__device__ __forceinline__ void upk(u64 v, float& lo, float& hi) {
    asm("mov.b64 {%0, %1}, %2;" : "=f"(lo), "=f"(hi) : "l"(v));
}
__device__ __forceinline__ u64 mul2(u64 a, u64 b) {
    u64 r; asm("mul.rn.f32x2 %0, %1, %2;" : "=l"(r) : "l"(a), "l"(b)); return r;
}
__device__ __forceinline__ u64 fma2(u64 a, u64 b, u64 c) {
    u64 r; asm("fma.rn.f32x2 %0, %1, %2, %3;" : "=l"(r) : "l"(a), "l"(b), "l"(c)); return r;
}
__device__ __forceinline__ void rotpair1(u64& fr, u64& fi, u64& sr, u64& si,
                                         float4 cc, float ctf, float stf) {
    u64 dr = pk2(cc.x), di = pk2(cc.y), orr = pk2(cc.z), oi = pk2(cc.w);
    u64 nd = di ^ SGN, no = oi ^ SGN, ct = pk2(ctf), st = pk2(stf);
    u64 ar = mul2(dr, fr); ar = fma2(nd, fi, ar);
    ar = fma2(orr, sr, ar); ar = fma2(no, si, ar);
    u64 ai = mul2(dr, fi); ai = fma2(di, fr, ai);
    ai = fma2(orr, si, ai); ai = fma2(oi, sr, ai);
    u64 br = mul2(ct, sr); br = fma2(st, fr, br);
    u64 bi = mul2(ct, si); bi = fma2(st, fi, bi);
    fr = ar; fi = ai; sr = br; si = bi;
}

__global__ void coeff_kernel(const float* __restrict__ phi0, const float* __restrict__ th0,
                             const float* __restrict__ phi1, const float* __restrict__ th1) {
    int idx = blockIdx.x * blockDim.x + threadIdx.x;
    if (idx >= NSTEP * 512) return;
    int p = idx & 511;
    int c = idx >> 9;
    int t = p >> 2;
    int k = p & 3;
    int base = c * 12 * NTH;
    float* F = (float*)gC;

    float sp, cp, st, ct;
    sincosf(phi0[p * NSTEP + c], &sp, &cp);
    sincosf(th0[p * NSTEP + c], &st, &ct);
    gC[base + k * NTH + t] = make_float4(cp * ct, sp * ct, -cp * st, -sp * st);
    {
        int chunk = 4 + (k >> 1), off = (k & 1) * 2;
        F[(base + chunk * NTH + t) * 4 + off]     = ct;
        F[(base + chunk * NTH + t) * 4 + off + 1] = st;
    }
    sincosf(phi1[p * NSTEP + c], &sp, &cp);
    sincosf(th1[p * NSTEP + c], &st, &ct);
    gC[base + (6 + k) * NTH + t] = make_float4(cp * ct, sp * ct, -cp * st, -sp * st);
    if (k < 2) {
        F[(base + 10 * NTH + t) * 4 + k * 2]     = ct;
        F[(base + 10 * NTH + t) * 4 + k * 2 + 1] = st;
    } else if (k == 2) {
        F[(base + 11 * NTH + t) * 4 + 0] = ct;
        F[(base + 11 * NTH + t) * 4 + 1] = st;
    } else {
        int ts = (t + 1) & (NTH - 1);
        F[(base + 11 * NTH + ts) * 4 + 2] = ct;
        F[(base + 11 * NTH + ts) * 4 + 3] = st;
    }
}

// ===================== U build: G=1 scan of the identity basis =====================
// 2 identity rows per block (f32x2 lanes); 512 blocks; identity synthesized in-kernel.
__device__ float gBmat[1024 * 2048];   // scan(identity): row j = U e_j (1024 x 1024 complex)

__global__ void __launch_bounds__(NTH, 6)
eunn_build(float4* __restrict__ xout) {
    const int t    = threadIdx.x;
    const int lane = t & 31;
    const int w    = t >> 5;
    const int row0 = blockIdx.x * 2;

    u64 er[8], ei[8];
    {
        const int td = row0 >> 3;     // thread holding both diagonal elements
        const int e0 = row0 & 7;      // row0 -> element e0; row0+1 -> e0+1 (row0 even)
#pragma unroll
        for (int e = 0; e < 8; e++) {
            float lo = (t == td && e == e0)     ? 1.0f : 0.0f;
            float hi = (t == td && e == e0 + 1) ? 1.0f : 0.0f;
            er[e] = pk(lo, hi);
            ei[e] = 0ULL;
        }
    }

    __shared__ u64 sE0r[2][4], sE0i[2][4], sE7r[2][4], sE7i[2][4];

    for (int c = 0; c < NSTEP; c++) {
        const int base = c * 12 * NTH + t;
        float4 k0 = gC[base + 0 * NTH], k1 = gC[base + 1 * NTH];
        float4 k2 = gC[base + 2 * NTH], k3 = gC[base + 3 * NTH];
        float4 k4 = gC[base + 4 * NTH], k5 = gC[base + 5 * NTH];

        rotpair1(er[0], ei[0], er[1], ei[1], k0, k4.x, k4.y);
        rotpair1(er[2], ei[2], er[3], ei[3], k1, k4.z, k4.w);
        rotpair1(er[4], ei[4], er[5], ei[5], k2, k5.x, k5.y);
        rotpair1(er[6], ei[6], er[7], ei[7], k3, k5.z, k5.w);

        const int buf = c & 1;
        if (lane == 0)  { sE0r[buf][w] = er[0]; sE0i[buf][w] = ei[0]; }
        if (lane == 31) { sE7r[buf][w] = er[7]; sE7i[buf][w] = ei[7]; }

        u64 nbr = __shfl_down_sync(0xffffffffu, er[0], 1);
        u64 nbi = __shfl_down_sync(0xffffffffu, ei[0], 1);
        u64 pvr = __shfl_up_sync(0xffffffffu, er[7], 1);
        u64 pvi = __shfl_up_sync(0xffffffffu, ei[7], 1);

        float4 k6 = gC[base + 6 * NTH], k7 = gC[base + 7 * NTH];
        float4 k8 = gC[base + 8 * NTH], k9 = gC[base + 9 * NTH];
        float4 kA = gC[base + 10 * NTH], kB = gC[base + 11 * NTH];

        rotpair1(er[1], ei[1], er[2], ei[2], k6, kA.x, kA.y);
        rotpair1(er[3], ei[3], er[4], ei[4], k7, kA.z, kA.w);
        rotpair1(er[5], ei[5], er[6], ei[6], k8, kB.x, kB.y);

        __syncthreads();

        {
            const int wn = (w + 1) & 3, wp = (w + 3) & 3;
            if (lane == 31) { nbr = sE0r[buf][wn]; nbi = sE0i[buf][wn]; }
            if (lane == 0)  { pvr = sE7r[buf][wp]; pvi = sE7i[buf][wp]; }

            u64 dr = pk2(k9.x), di = pk2(k9.y), orr = pk2(k9.z), oi = pk2(k9.w);
            u64 nd = di ^ SGN, no = oi ^ SGN, ctm = pk2(kB.z), stm = pk2(kB.w);

            u64 cr = mul2(dr, er[7]); cr = fma2(nd, ei[7], cr);
            cr = fma2(orr, nbr, cr);  cr = fma2(no, nbi, cr);
            u64 ci = mul2(dr, ei[7]); ci = fma2(di, er[7], ci);
            ci = fma2(orr, nbi, ci);  ci = fma2(oi, nbr, ci);
            u64 zr = mul2(ctm, er[0]); zr = fma2(stm, pvr, zr);
            u64 zi = mul2(ctm, ei[0]); zi = fma2(stm, pvi, zi);
            er[7] = cr; ei[7] = ci; er[0] = zr; ei[0] = zi;
        }
    }

    {
        size_t r0 = (size_t)row0 * 512;
        size_t r1 = r0 + 512;
#pragma unroll
        for (int j = 0; j < 4; j++) {
            float4 a, b;
            upk(er[2 * j], a.x, b.x);     upk(ei[2 * j], a.y, b.y);
            upk(er[2 * j + 1], a.z, b.z); upk(ei[2 * j + 1], a.w, b.w);
            xout[r0 + 4 * t + j] = a;
            xout[r1 + 4 * t + j] = b;
        }
    }
}

// ===================== conversions =====================
__device__ __nv_bfloat16 gXh[4096u * 2048u];
__device__ __nv_bfloat16 gXl[4096u * 2048u];
__device__ __nv_bfloat16 gWtH[2048u * 2048u];   // row n = output col, col k = input col
__device__ __nv_bfloat16 gWtL[2048u * 2048u];

// Wt[2i][2j]=Ure  Wt[2i][2j+1]=-Uim  Wt[2i+1][2j]=Uim  Wt[2i+1][2j+1]=Ure,  U[i][j]=gBmat[j][i]
// smem-transposed: coalesced float2 reads AND coalesced bf16x2 writes.
__global__ void convert_w() {
    __shared__ float2 tile[32][33];
    const int tx = threadIdx.x, ty = threadIdx.y;
    {
        int i = blockIdx.x * 32 + tx;       // coalesced read along i
        int j = blockIdx.y * 32 + ty;
        tile[ty][tx] = ((const float2*)gBmat)[j * 1024 + i];
    }
    __syncthreads();
    const int i = blockIdx.x * 32 + ty;
    const int j = blockIdx.y * 32 + tx;     // coalesced write along j
    float2 v = tile[tx][ty];
    float re = v.x, im = v.y;
    __nv_bfloat16 reh = __float2bfloat16(re);
    __nv_bfloat16 rel = __float2bfloat16(re - __bfloat162float(reh));
    __nv_bfloat16 imh = __float2bfloat16(im);
    __nv_bfloat16 iml = __float2bfloat16(im - __bfloat162float(imh));
    __nv_bfloat16 nimh = __float2bfloat16(-__bfloat162float(imh));
    __nv_bfloat16 niml = __float2bfloat16(-__bfloat162float(iml));
    size_t o0 = (size_t)(2 * i) * 2048 + 2 * j;
    size_t o1 = o0 + 2048;
    __nv_bfloat162 q;
    q.x = reh; q.y = nimh; *(__nv_bfloat162*)(gWtH + o0) = q;
    q.x = imh; q.y = reh;  *(__nv_bfloat162*)(gWtH + o1) = q;
    q.x = rel; q.y = niml; *(__nv_bfloat162*)(gWtL + o0) = q;
    q.x = iml; q.y = rel;  *(__nv_bfloat162*)(gWtL + o1) = q;
}

__global__ void convert_x(const float* __restrict__ x) {
    int idx = blockIdx.x * blockDim.x + threadIdx.x;
    float v = x[idx];
    __nv_bfloat16 h = __float2bfloat16(v);
    gXh[idx] = h;
    gXl[idx] = __float2bfloat16(v - __bfloat162float(h));
}

// ===================== mma.sync bf16 GEMM (unchanged from R16, passing) =====================
#define ROWB   80
#define AH_OFF 0
#define AL_OFF 10240
#define BH_OFF 20480
#define BL_OFF 25600
#define STAGE  30720

__device__ __forceinline__ uint32_t smem_to_u32(const void* p) {
    uint32_t a;
    asm("{ .reg .u64 t; cvta.to.shared.u64 t, %1; cvt.u32.u64 %0, t; }" : "=r"(a) : "l"(p));
    return a;
}
__device__ __forceinline__ void cp16(uint32_t dst, const __nv_bfloat16* src) {
    uint64_t g; asm("cvta.to.global.u64 %0, %1;" : "=l"(g) : "l"(src));
    asm volatile("cp.async.cg.shared.global [%0], [%1], 16;" :: "r"(dst), "l"(g));
}
#define CP_COMMIT() asm volatile("cp.async.commit_group;")
#define CP_WAIT(n)  asm volatile("cp.async.wait_group %0;" :: "n"(n))

__device__ __forceinline__ void ldsm_x4(uint32_t* r, uint32_t addr) {
    asm volatile("ldmatrix.sync.aligned.m8n8.x4.shared.b16 {%0,%1,%2,%3}, [%4];"
        : "=r"(r[0]), "=r"(r[1]), "=r"(r[2]), "=r"(r[3]) : "r"(addr));
}
__device__ __forceinline__ void ldsm_x2(uint32_t* r, uint32_t addr) {
    asm volatile("ldmatrix.sync.aligned.m8n8.x2.shared.b16 {%0,%1}, [%2];"
        : "=r"(r[0]), "=r"(r[1]) : "r"(addr));
}
__device__ __forceinline__ void mma_bf16(float* c, const uint32_t* a, const uint32_t* b) {
    asm volatile("mma.sync.aligned.m16n8k16.row.col.f32.bf16.bf16.f32 "
        "{%0,%1,%2,%3}, {%4,%5,%6,%7}, {%8,%9}, {%0,%1,%2,%3};"
        : "+f"(c[0]), "+f"(c[1]), "+f"(c[2]), "+f"(c[3])
        : "r"(a[0]), "r"(a[1]), "r"(a[2]), "r"(a[3]), "r"(b[0]), "r"(b[1]));
}

__global__ void __launch_bounds__(256)
gemm_kernel(float* __restrict__ out) {
    extern __shared__ unsigned char smemBuf[];
    const uint32_t sbase = smem_to_u32(smemBuf);
    const int tid  = threadIdx.x;
    const int lane = tid & 31;
    const int wid  = tid >> 5;
    const int wm   = wid & 3;
    const int wn   = wid >> 2;
    const int m0   = blockIdx.x * 128;
    const int n0   = blockIdx.y * 64;

    auto load_stage = [&](int st, int it) {
        uint32_t sb = sbase + st * STAGE;
        int k0 = it * 32;
#pragma unroll
        for (int h = 0; h < 2; h++) {
            int c = tid + h * 256;
            int row = c >> 2, seg = c & 3;
            size_t go = (size_t)(m0 + row) * 2048 + k0 + seg * 8;
            uint32_t d = sb + row * ROWB + seg * 16;
            cp16(d + AH_OFF, gXh + go);
            cp16(d + AL_OFF, gXl + go);
        }
        {
            int row = tid >> 2, seg = tid & 3;
            size_t go = (size_t)(n0 + row) * 2048 + k0 + seg * 8;
            uint32_t d = sb + row * ROWB + seg * 16;
            cp16(d + BH_OFF, gWtH + go);
            cp16(d + BL_OFF, gWtL + go);
        }
        CP_COMMIT();
    };

    float acc[2][4][4];
#pragma unroll
    for (int mf = 0; mf < 2; mf++)
#pragma unroll
        for (int nf = 0; nf < 4; nf++)
#pragma unroll
            for (int q = 0; q < 4; q++) acc[mf][nf][q] = 0.0f;

    load_stage(0, 0);

    for (int it = 0; it < 64; it++) {
        if (it < 63) { load_stage((it + 1) & 1, it + 1); CP_WAIT(1); }
        else         { CP_WAIT(0); }
        __syncthreads();

        uint32_t sb = sbase + (it & 1) * STAGE;
#pragma unroll
        for (int kk = 0; kk < 32; kk += 16) {
            uint32_t ah[2][4], al[2][4], bh[4][2], bl[4][2];
#pragma unroll
            for (int mf = 0; mf < 2; mf++) {
                uint32_t row = wm * 32 + mf * 16 + (lane & 15);
                uint32_t col = kk + (lane >> 4) * 8;
                uint32_t off = row * ROWB + col * 2;
                ldsm_x4(ah[mf], sb + AH_OFF + off);
                ldsm_x4(al[mf], sb + AL_OFF + off);
            }
#pragma unroll
            for (int nf = 0; nf < 4; nf++) {
                int l = lane & 15;
                uint32_t nrow = wn * 32 + nf * 8 + (l & 7);
                uint32_t col = kk + ((l >> 3) & 1) * 8;
                uint32_t off = nrow * ROWB + col * 2;
                ldsm_x2(bh[nf], sb + BH_OFF + off);
                ldsm_x2(bl[nf], sb + BL_OFF + off);
            }
#pragma unroll
            for (int mf = 0; mf < 2; mf++)
#pragma unroll
                for (int nf = 0; nf < 4; nf++) {
                    mma_bf16(acc[mf][nf], ah[mf], bh[nf]);
                    mma_bf16(acc[mf][nf], ah[mf], bl[nf]);
                    mma_bf16(acc[mf][nf], al[mf], bh[nf]);
                }
        }
        __syncthreads();
    }

#pragma unroll
    for (int mf = 0; mf < 2; mf++)
#pragma unroll
        for (int nf = 0; nf < 4; nf++) {
            int r    = m0 + wm * 32 + mf * 16 + (lane >> 2);
            int ccol = n0 + wn * 32 + nf * 8 + (lane & 3) * 2;
            *(float2*)(out + (size_t)r * 2048 + ccol) =
                make_float2(acc[mf][nf][0], acc[mf][nf][1]);
            *(float2*)(out + (size_t)(r + 8) * 2048 + ccol) =
                make_float2(acc[mf][nf][2], acc[mf][nf][3]);
        }
}

// ===================== launch =====================
extern "C" void kernel_launch(void* const* d_in, const int* in_sizes, int n_in,
                              void* d_out, int out_size) {
    const float* x    = (const float*)d_in[0];
    const float* phi0 = (const float*)d_in[1];
    const float* th0  = (const float*)d_in[2];
    const float* phi1 = (const float*)d_in[3];
    const float* th1  = (const float*)d_in[4];

    coeff_kernel<<<(NSTEP * 512 + 255) / 256, 256>>>(phi0, th0, phi1, th1);

    void* pB = nullptr;
    cudaGetSymbolAddress(&pB, gBmat);
    // Build U by scanning the identity basis (identity synthesized in-kernel).
    eunn_build<<<512, NTH>>>((float4*)pB);

    convert_w<<<dim3(32, 32), dim3(32, 32)>>>();
    convert_x<<<(4096 * 2048) / 256, 256>>>(x);

    cudaFuncSetAttribute(gemm_kernel, cudaFuncAttributeMaxDynamicSharedMemorySize, 2 * STAGE);
    gemm_kernel<<<dim3(32, 32, 1), 256, 2 * STAGE>>>((float*)d_out);
}